// round 2
// baseline (speedup 1.0000x reference)
#include <cuda_runtime.h>
#include <cuda_bf16.h>
#include <math.h>

// ---------------- problem constants ----------------
#define BATCH   2
#define LSEQ    1024
#define DMODEL  512
#define DINNER  1024
#define DSTATE  64
#define DTRANK  32
#define XPROJ_N (DTRANK + 2*DSTATE)   // 160
#define ROWS    (BATCH*LSEQ)          // 2048
#define EPSV    1e-6f

// ---------------- scratch (device globals; no allocations allowed) ----------------
__device__ float g_h   [ROWS*DMODEL];        // rmsnorm(x)
__device__ float g_xz  [ROWS*2*DINNER];      // h @ W_in^T   (u | z)
__device__ float g_u   [2][ROWS*DINNER];     // conv+silu per direction
__device__ float g_xdbl[2][ROWS*XPROJ_N];    // u @ W_xproj^T
__device__ float g_dt  [2][ROWS*DINNER];     // softplus(dt)
__device__ float g_gate[2][ROWS*DINNER];     // (y + u*Dskip)*silu(z)
__device__ float g_hcat[ROWS*2*DMODEL];      // [hf | hb]
__device__ float g_uv  [ROWS*2*DMODEL];      // fuse output
__device__ float g_h2  [ROWS*DMODEL];        // silu(ug*sigmoid(vg))
__device__ float g_ff1 [ROWS*4*DMODEL];      // silu(h2 @ ff_W1^T)
__device__ float g_ff2 [ROWS*DMODEL];        // ff1s @ ff_W2^T

// ---------------- math helpers ----------------
__device__ __forceinline__ float sigmoidf_(float x){ return 1.0f/(1.0f+expf(-x)); }
__device__ __forceinline__ float siluf_(float x){ return x/(1.0f+expf(-x)); }
__device__ __forceinline__ float softplusf_(float x){ return (x>20.0f)? x : log1pf(expf(x)); }

// ---------------- rmsnorm: one block per row of 512 ----------------
__global__ void rmsnorm_kernel(const float* __restrict__ x,
                               const float* __restrict__ addsrc,
                               const float* __restrict__ w,
                               float* __restrict__ out)
{
    int row = blockIdx.x;
    int t = threadIdx.x;                       // 128 threads, 4 floats each
    const float4* x4 = (const float4*)(x + (size_t)row*DMODEL);
    float4 v = x4[t];
    if (addsrc){
        const float4* a4 = (const float4*)(addsrc + (size_t)row*DMODEL);
        float4 a = a4[t];
        v.x+=a.x; v.y+=a.y; v.z+=a.z; v.w+=a.w;
    }
    float ss = v.x*v.x + v.y*v.y + v.z*v.z + v.w*v.w;
    #pragma unroll
    for (int o=16;o;o>>=1) ss += __shfl_xor_sync(0xffffffffu, ss, o);
    __shared__ float sacc[4];
    if ((t&31)==0) sacc[t>>5] = ss;
    __syncthreads();
    float tot = sacc[0]+sacc[1]+sacc[2]+sacc[3];
    float rinv = rsqrtf(tot*(1.0f/(float)DMODEL) + EPSV);
    const float4* w4 = (const float4*)w;
    float4 wv = w4[t];
    float4 o4 = make_float4(v.x*rinv*wv.x, v.y*rinv*wv.y, v.z*rinv*wv.z, v.w*rinv*wv.w);
    ((float4*)(out + (size_t)row*DMODEL))[t] = o4;
}

// ---------------- generic tiled GEMM: C[M,N] = A[M,K] @ W[N,K]^T (+epilogue) ----------------
// EPI: 0 none, 1 silu, 2 softplus(acc+bias), 3 acc+bias
template<int EPI>
__global__ __launch_bounds__(256)
void gemm_kernel(const float* __restrict__ A, int lda,
                 const float* __restrict__ W,
                 const float* __restrict__ bias,
                 float* __restrict__ C, int ldc,
                 int N, int K)
{
    __shared__ __align__(16) float As[16][68];
    __shared__ __align__(16) float Ws[16][68];
    int m0 = blockIdx.y*64, n0 = blockIdx.x*64;
    int t  = threadIdx.x;
    int lr = t>>2;             // 0..63
    int lk = (t&3)*4;          // 0,4,8,12
    int tx = t&15, ty = t>>4;  // 16x16 threads, 4x4 microtile
    float acc[4][4] = {};

    for (int k0=0; k0<K; k0+=16){
        float4 av = *(const float4*)&A[(size_t)(m0+lr)*lda + k0 + lk];
        int gn = n0 + lr;
        float4 wv = make_float4(0.f,0.f,0.f,0.f);
        if (gn < N) wv = *(const float4*)&W[(size_t)gn*K + k0 + lk];
        __syncthreads();
        As[lk+0][lr]=av.x; As[lk+1][lr]=av.y; As[lk+2][lr]=av.z; As[lk+3][lr]=av.w;
        Ws[lk+0][lr]=wv.x; Ws[lk+1][lr]=wv.y; Ws[lk+2][lr]=wv.z; Ws[lk+3][lr]=wv.w;
        __syncthreads();
        #pragma unroll
        for (int k=0;k<16;k++){
            float4 a = *(const float4*)&As[k][ty*4];
            float4 b = *(const float4*)&Ws[k][tx*4];
            acc[0][0] += a.x*b.x; acc[0][1] += a.x*b.y; acc[0][2] += a.x*b.z; acc[0][3] += a.x*b.w;
            acc[1][0] += a.y*b.x; acc[1][1] += a.y*b.y; acc[1][2] += a.y*b.z; acc[1][3] += a.y*b.w;
            acc[2][0] += a.z*b.x; acc[2][1] += a.z*b.y; acc[2][2] += a.z*b.z; acc[2][3] += a.z*b.w;
            acc[3][0] += a.w*b.x; acc[3][1] += a.w*b.y; acc[3][2] += a.w*b.z; acc[3][3] += a.w*b.w;
        }
    }
    #pragma unroll
    for (int i=0;i<4;i++){
        int gm = m0 + ty*4 + i;
        #pragma unroll
        for (int j=0;j<4;j++){
            int gn = n0 + tx*4 + j;
            if (gn < N){
                float v = acc[i][j];
                if (EPI==1) v = siluf_(v);
                else if (EPI==2) v = softplusf_(v + bias[gn]);
                else if (EPI==3) v = v + bias[gn];
                C[(size_t)gm*ldc + gn] = v;
            }
        }
    }
}

// ---------------- depthwise causal conv (both directions) + bias + silu ----------------
__global__ void conv_kernel(const float* __restrict__ cw, const float* __restrict__ cb)
{
    int idx = blockIdx.x*256 + threadIdx.x;      // over ROWS*DINNER
    if (idx >= ROWS*DINNER) return;
    int d = idx & (DINNER-1);
    int r = idx >> 10;
    int l = r & (LSEQ-1);
    int b = r >> 10;
    float w0=cw[d*4+0], w1=cw[d*4+1], w2=cw[d*4+2], w3=cw[d*4+3];
    float bias = cb[d];
    const float* up = g_xz + (size_t)(b<<10)*(2*DINNER) + d;  // u[l'] = up[l'*2048]
    auto U = [&](int li)->float{ return (li>=0 && li<LSEQ) ? up[(size_t)li*(2*DINNER)] : 0.0f; };
    float um3=U(l-3), um2=U(l-2), um1=U(l-1), u0=U(l), up1=U(l+1), up2=U(l+2), up3=U(l+3);
    // forward: causal.  backward: conv of flipped seq, written at original l
    float f  = bias + w0*um3 + w1*um2 + w2*um1 + w3*u0;
    float bw = bias + w3*u0  + w2*up1 + w1*up2 + w0*up3;
    g_u[0][idx] = siluf_(f);
    g_u[1][idx] = siluf_(bw);
}

// ---------------- selective scan: one warp per (dir, b, d) ----------------
__global__ void scan_kernel(const float* __restrict__ A_log, const float* __restrict__ Dskip)
{
    int w    = (blockIdx.x*blockDim.x + threadIdx.x) >> 5;
    int lane = threadIdx.x & 31;
    int dir  = w >> 11;           // 2048 warps per direction
    int rem  = w & 2047;
    int b    = rem >> 10;
    int d    = rem & 1023;
    const float* dtp = g_dt[dir];
    const float* up  = g_u[dir];
    const float* xd  = g_xdbl[dir];
    float* gp        = g_gate[dir];

    int n0 = lane*2;
    float a0 = -expf(A_log[d*DSTATE + n0]);
    float a1 = -expf(A_log[d*DSTATE + n0 + 1]);
    float dsk = Dskip[d];
    float s0 = 0.f, s1 = 0.f;
    int base_r = b << 10;

    for (int t=0; t<LSEQ; t++){
        int l = dir ? (LSEQ-1-t) : t;
        int r = base_r + l;
        float dtv = __ldg(&dtp[(size_t)r*DINNER + d]);
        float uu  = __ldg(&up [(size_t)r*DINNER + d]);
        float2 Bv = *(const float2*)&xd[(size_t)r*XPROJ_N + DTRANK + n0];
        float2 Cv = *(const float2*)&xd[(size_t)r*XPROJ_N + DTRANK + DSTATE + n0];
        float dA0 = __expf(dtv*a0);
        float dA1 = __expf(dtv*a1);
        float dtu = dtv*uu;
        s0 = fmaf(s0, dA0, dtu*Bv.x);
        s1 = fmaf(s1, dA1, dtu*Bv.y);
        float p = s0*Cv.x + s1*Cv.y;
        #pragma unroll
        for (int o=16;o;o>>=1) p += __shfl_xor_sync(0xffffffffu, p, o);
        if (lane==0){
            float z = g_xz[(size_t)r*(2*DINNER) + DINNER + d];
            float y = p + uu*dsk;
            gp[(size_t)r*DINNER + d] = y * (z/(1.0f+__expf(-z)));
        }
    }
}

// ---------------- GLU gate + silu ----------------
__global__ void glu_kernel()
{
    int idx = blockIdx.x*256 + threadIdx.x;    // over ROWS*DMODEL
    if (idx >= ROWS*DMODEL) return;
    int r = idx >> 9;
    int d = idx & (DMODEL-1);
    float ug = g_uv[(size_t)r*(2*DMODEL) + d];
    float vg = g_uv[(size_t)r*(2*DMODEL) + DMODEL + d];
    float h  = ug * sigmoidf_(vg);
    g_h2[idx] = siluf_(h);
}

// ---------------- host side ----------------
static float* sym_addr(const void* sym)
{
    void* p = nullptr;
    cudaGetSymbolAddress(&p, sym);
    return (float*)p;
}

extern "C" void kernel_launch(void* const* d_in, const int* in_sizes, int n_in,
                              void* d_out, int out_size)
{
    const float* x       = (const float*)d_in[0];
    const float* W_in    = (const float*)d_in[1];
    const float* conv_w  = (const float*)d_in[2];
    const float* conv_b  = (const float*)d_in[3];
    const float* W_xproj = (const float*)d_in[4];
    const float* W_dt    = (const float*)d_in[5];
    const float* b_dt    = (const float*)d_in[6];
    const float* A_log   = (const float*)d_in[7];
    const float* Dskip   = (const float*)d_in[8];
    const float* W_out   = (const float*)d_in[9];
    const float* nin_w   = (const float*)d_in[10];
    const float* fuse_W  = (const float*)d_in[11];
    const float* fuse_b  = (const float*)d_in[12];
    const float* ff_W1   = (const float*)d_in[13];
    const float* ff_W2   = (const float*)d_in[14];
    const float* nout_w  = (const float*)d_in[15];
    float* out = (float*)d_out;

    float* p_h    = sym_addr(g_h);
    float* p_xz   = sym_addr(g_xz);
    float* p_u    = sym_addr(g_u);        // [2][ROWS*DINNER] contiguous
    float* p_xdbl = sym_addr(g_xdbl);
    float* p_dt   = sym_addr(g_dt);
    float* p_gate = sym_addr(g_gate);
    float* p_hcat = sym_addr(g_hcat);
    float* p_uv   = sym_addr(g_uv);
    float* p_h2   = sym_addr(g_h2);
    float* p_ff1  = sym_addr(g_ff1);
    float* p_ff2  = sym_addr(g_ff2);

    dim3 blk(256);

    // 1. h = rmsnorm(x)
    rmsnorm_kernel<<<ROWS, 128>>>(x, nullptr, nin_w, p_h);

    // 2. xz = h @ W_in^T   (M=2048, N=2048, K=512)
    gemm_kernel<0><<<dim3(32,32), blk>>>(p_h, DMODEL, W_in, nullptr, p_xz, 2*DINNER, 2*DINNER, DMODEL);

    // 3. conv + silu, both directions
    conv_kernel<<<(ROWS*DINNER)/256, blk>>>(conv_w, conv_b);

    // 4/5. per direction: x_dbl, dt
    for (int dir=0; dir<2; dir++){
        float* u_d    = p_u    + (size_t)dir*ROWS*DINNER;
        float* xdbl_d = p_xdbl + (size_t)dir*ROWS*XPROJ_N;
        float* dt_d   = p_dt   + (size_t)dir*ROWS*DINNER;
        // x_dbl = u @ W_xproj^T  (N=160, K=1024)
        gemm_kernel<0><<<dim3(3,32), blk>>>(u_d, DINNER, W_xproj, nullptr, xdbl_d, XPROJ_N, XPROJ_N, DINNER);
        // dt = softplus(x_dbl[:, :32] @ W_dt^T + b_dt)  (N=1024, K=32, lda=160)
        gemm_kernel<2><<<dim3(16,32), blk>>>(xdbl_d, XPROJ_N, W_dt, b_dt, dt_d, DINNER, DINNER, DTRANK);
    }

    // 6. selective scan (both directions) -> gate = (y + u*Dskip)*silu(z)
    scan_kernel<<<512, 256>>>(A_log, Dskip);

    // 7. hcat[:, dir*512 : ] = gate_dir @ W_out^T  (N=512, K=1024)
    for (int dir=0; dir<2; dir++){
        float* gate_d = p_gate + (size_t)dir*ROWS*DINNER;
        gemm_kernel<0><<<dim3(8,32), blk>>>(gate_d, DINNER, W_out, nullptr,
                                            p_hcat + dir*DMODEL, 2*DMODEL, DMODEL, DINNER);
    }

    // 8. uv = hcat @ fuse_W^T + fuse_b  (N=1024, K=1024)
    gemm_kernel<3><<<dim3(16,32), blk>>>(p_hcat, 2*DMODEL, fuse_W, fuse_b, p_uv, 2*DMODEL, 2*DMODEL, 2*DMODEL);

    // 9. h2 = silu(ug * sigmoid(vg))
    glu_kernel<<<(ROWS*DMODEL)/256, blk>>>();

    // 10. ff1 = silu(h2 @ ff_W1^T)  (N=2048, K=512)
    gemm_kernel<1><<<dim3(32,32), blk>>>(p_h2, DMODEL, ff_W1, nullptr, p_ff1, 4*DMODEL, 4*DMODEL, DMODEL);

    // 11. ff2 = ff1 @ ff_W2^T  (N=512, K=2048)
    gemm_kernel<0><<<dim3(8,32), blk>>>(p_ff1, 4*DMODEL, ff_W2, nullptr, p_ff2, DMODEL, DMODEL, 4*DMODEL);

    // 12. out = rmsnorm(x + ff2)
    rmsnorm_kernel<<<ROWS, 128>>>(x, p_ff2, nout_w, out);
}

// round 4
// speedup vs baseline: 1.6746x; 1.6746x over previous
#include <cuda_runtime.h>
#include <cuda_bf16.h>
#include <math.h>
#include <stdint.h>

// ---------------- problem constants ----------------
#define BATCH   2
#define LSEQ    1024
#define DMODEL  512
#define DINNER  1024
#define DSTATE  64
#define DTRANK  32
#define ROWS    (BATCH*LSEQ)          // 2048
#define EPSV    1e-6f

// ---------------- scratch (device globals; no allocations allowed) ----------------
__device__ __align__(16) __nv_bfloat16 g_h_b   [ROWS*DMODEL];      // rmsnorm(x) bf16
__device__ __align__(16) float         g_xz    [ROWS*2*DINNER];    // h @ W_in^T (u | z) fp32
__device__ __align__(16) __nv_bfloat16 g_u_b   [2][ROWS*DINNER];   // conv+silu bf16
__device__ __align__(16) float         g_xdbl  [2][ROWS*128];      // [B|C] fp32 (128 cols)
__device__ __align__(16) float         g_dt    [2][ROWS*DINNER];   // softplus(dt) fp32
__device__ __align__(16) __nv_bfloat16 g_gate_b[2][ROWS*DINNER];   // (y+u*D)*silu(z) bf16
__device__ __align__(16) __nv_bfloat16 g_hcat_b[ROWS*2*DMODEL];    // [hf|hb] bf16
__device__ __align__(16) float         g_uv    [ROWS*2*DMODEL];    // fuse out fp32
__device__ __align__(16) __nv_bfloat16 g_h2_b  [ROWS*DMODEL];      // silu(glu) bf16
__device__ __align__(16) __nv_bfloat16 g_ff1_b [ROWS*4*DMODEL];    // silu(ff1) bf16
__device__ __align__(16) float         g_ff2   [ROWS*DMODEL];      // ff2 fp32
// bf16 weights
__device__ __align__(16) __nv_bfloat16 g_Win_b [2*DINNER*DMODEL];
__device__ __align__(16) __nv_bfloat16 g_Wxp_b [128*DINNER];       // W_xproj rows 32..159
__device__ __align__(16) __nv_bfloat16 g_Wcomb_b[DINNER*DINNER];   // W_dt @ W_xproj[:32]
__device__ __align__(16) __nv_bfloat16 g_Wout_b[DMODEL*DINNER];
__device__ __align__(16) __nv_bfloat16 g_fuse_b[2*DMODEL*2*DMODEL];
__device__ __align__(16) __nv_bfloat16 g_ff1w_b[4*DMODEL*DMODEL];
__device__ __align__(16) __nv_bfloat16 g_ff2w_b[DMODEL*4*DMODEL];

// ---------------- math helpers ----------------
__device__ __forceinline__ float sigmoidf_(float x){ return 1.0f/(1.0f+expf(-x)); }
__device__ __forceinline__ float siluf_(float x){ return x/(1.0f+expf(-x)); }
__device__ __forceinline__ float softplusf_(float x){ return (x>20.0f)? x : log1pf(expf(x)); }

__device__ __forceinline__ uint32_t smem_u32_(const void* p){
    uint32_t a;
    asm("{ .reg .u64 t; cvta.to.shared.u64 t, %1; cvt.u32.u64 %0, t; }" : "=r"(a) : "l"(p));
    return a;
}

// ---------------- mma.sync bf16 GEMM: C[M,N] = A[M,K](bf16) @ W[N,K](bf16)^T ----------------
// 128x128 CTA tile, 8 warps (2 x 4), warp tile 64x32.
// K chunk = 64 (double buffered cp.async). smem rows padded to 72 bf16 (144B).
// EPI: 0 none, 1 silu, 2 softplus(+bias), 3 +bias
#define KCHUNK  64
#define SROW    72                        // bf16 elements per smem row (padded)
#define CHUNK_BYTES (128*SROW*2)          // 18432 per matrix per buffer
#define GEMM_SMEM (4*CHUNK_BYTES)         // A+B, double buffered = 73728

__device__ __forceinline__ void ldsm_x4(uint32_t& r0, uint32_t& r1, uint32_t& r2, uint32_t& r3, uint32_t a){
    asm volatile("ldmatrix.sync.aligned.m8n8.x4.shared.b16 {%0,%1,%2,%3},[%4];"
                 : "=r"(r0),"=r"(r1),"=r"(r2),"=r"(r3) : "r"(a));
}
__device__ __forceinline__ void ldsm_x2(uint32_t& r0, uint32_t& r1, uint32_t a){
    asm volatile("ldmatrix.sync.aligned.m8n8.x2.shared.b16 {%0,%1},[%2];"
                 : "=r"(r0),"=r"(r1) : "r"(a));
}
__device__ __forceinline__ void mma16816(float* d, const uint32_t* a, const uint32_t* b){
    asm volatile("mma.sync.aligned.m16n8k16.row.col.f32.bf16.bf16.f32 "
                 "{%0,%1,%2,%3},{%4,%5,%6,%7},{%8,%9},{%0,%1,%2,%3};"
                 : "+f"(d[0]),"+f"(d[1]),"+f"(d[2]),"+f"(d[3])
                 : "r"(a[0]),"r"(a[1]),"r"(a[2]),"r"(a[3]), "r"(b[0]),"r"(b[1]));
}

template<int EPI, typename OutT>
__global__ void __launch_bounds__(256)
tc_gemm(const __nv_bfloat16* __restrict__ A,
        const __nv_bfloat16* __restrict__ W,
        const float* __restrict__ bias,
        OutT* __restrict__ C, int ldc, int K)
{
    extern __shared__ char smem[];
    uint32_t sb = smem_u32_(smem);
    int tid = threadIdx.x, lane = tid & 31, w = tid >> 5;
    int wm = w >> 2, wn = w & 3;              // 2 x 4 warp grid
    int m0 = blockIdx.y*128, n0 = blockIdx.x*128;

    const __nv_bfloat16* Abase = A + (size_t)m0*K;
    const __nv_bfloat16* Wbase = W + (size_t)n0*K;
    const int NC = K / KCHUNK;

    auto load_chunk = [&](int c, int b){
        uint32_t abuf = sb + (uint32_t)b*2*CHUNK_BYTES;
        uint32_t bbuf = abuf + CHUNK_BYTES;
        const __nv_bfloat16* Ag = Abase + c*KCHUNK;
        const __nv_bfloat16* Wg = Wbase + c*KCHUNK;
        #pragma unroll
        for (int i=0;i<4;i++){
            int idx = i*256 + tid;            // 0..1023
            int r = idx>>3, cc = idx&7;       // row, 16B chunk within 128B row
            uint32_t dst = (uint32_t)(r*(SROW*2) + cc*16);
            asm volatile("cp.async.cg.shared.global [%0],[%1],16;"
                         :: "r"(abuf+dst), "l"((const void*)(Ag + (size_t)r*K + cc*8)));
            asm volatile("cp.async.cg.shared.global [%0],[%1],16;"
                         :: "r"(bbuf+dst), "l"((const void*)(Wg + (size_t)r*K + cc*8)));
        }
        asm volatile("cp.async.commit_group;");
    };

    float acc[4][4][4];
    #pragma unroll
    for (int i=0;i<4;i++)
        #pragma unroll
        for (int j=0;j<4;j++)
            #pragma unroll
            for (int q=0;q<4;q++) acc[i][j][q]=0.f;

    // per-lane ldmatrix address components (bf16-element offsets, x2 bytes later)
    int a_row  = wm*64 + (lane & 15);         // + mt*16
    int a_koff = (lane >> 4) * 8;             // + kstep*16
    int b_row  = wn*32 + (lane & 7);          // + nt*8
    int b_koff = ((lane >> 3) & 1) * 8;       // + kstep*16

    load_chunk(0,0);
    if (NC>1) load_chunk(1,1);

    for (int c=0;c<NC;c++){
        int b = c&1;
        if (c+1<NC) asm volatile("cp.async.wait_group 1;" ::: "memory");
        else        asm volatile("cp.async.wait_group 0;" ::: "memory");
        __syncthreads();
        uint32_t abuf = sb + (uint32_t)b*2*CHUNK_BYTES;
        uint32_t bbuf = abuf + CHUNK_BYTES;
        #pragma unroll
        for (int ks=0; ks<KCHUNK/16; ks++){
            uint32_t afr[4][4], bfr[4][2];
            #pragma unroll
            for (int mt=0;mt<4;mt++){
                uint32_t addr = abuf + (uint32_t)(((a_row + mt*16)*SROW + ks*16 + a_koff)*2);
                ldsm_x4(afr[mt][0],afr[mt][1],afr[mt][2],afr[mt][3], addr);
            }
            #pragma unroll
            for (int nt=0;nt<4;nt++){
                uint32_t addr = bbuf + (uint32_t)(((b_row + nt*8)*SROW + ks*16 + b_koff)*2);
                ldsm_x2(bfr[nt][0],bfr[nt][1], addr);
            }
            #pragma unroll
            for (int mt=0;mt<4;mt++)
                #pragma unroll
                for (int nt=0;nt<4;nt++)
                    mma16816(acc[mt][nt], afr[mt], bfr[nt]);
        }
        __syncthreads();
        if (c+2<NC) load_chunk(c+2, b);
    }

    // epilogue: fragment layout -> global
    int rbase = m0 + wm*64 + (lane>>2);
    int cbase = n0 + wn*32 + (lane&3)*2;
    #pragma unroll
    for (int mt=0;mt<4;mt++){
        #pragma unroll
        for (int nt=0;nt<4;nt++){
            int col = cbase + nt*8;
            float v[4];
            #pragma unroll
            for (int q=0;q<4;q++){
                float x = acc[mt][nt][q];
                int cc = col + (q&1);
                if (EPI==1) x = siluf_(x);
                else if (EPI==2) x = softplusf_(x + bias[cc]);
                else if (EPI==3) x = x + bias[cc];
                v[q] = x;
            }
            int r0 = rbase + mt*16, r1 = r0 + 8;
            if (sizeof(OutT)==4){
                *(float2*)((float*)C + (size_t)r0*ldc + col) = make_float2(v[0],v[1]);
                *(float2*)((float*)C + (size_t)r1*ldc + col) = make_float2(v[2],v[3]);
            } else {
                *(__nv_bfloat162*)((__nv_bfloat16*)C + (size_t)r0*ldc + col) = __floats2bfloat162_rn(v[0],v[1]);
                *(__nv_bfloat162*)((__nv_bfloat16*)C + (size_t)r1*ldc + col) = __floats2bfloat162_rn(v[2],v[3]);
            }
        }
    }
}

// ---------------- rmsnorm: one block per row of 512, templated output ----------------
template<typename OutT>
__global__ void rmsnorm_kernel(const float* __restrict__ x,
                               const float* __restrict__ addsrc,
                               const float* __restrict__ w,
                               OutT* __restrict__ out)
{
    int row = blockIdx.x;
    int t = threadIdx.x;                       // 128 threads, 4 floats each
    const float4* x4 = (const float4*)(x + (size_t)row*DMODEL);
    float4 v = x4[t];
    if (addsrc){
        const float4* a4 = (const float4*)(addsrc + (size_t)row*DMODEL);
        float4 a = a4[t];
        v.x+=a.x; v.y+=a.y; v.z+=a.z; v.w+=a.w;
    }
    float ss = v.x*v.x + v.y*v.y + v.z*v.z + v.w*v.w;
    #pragma unroll
    for (int o=16;o;o>>=1) ss += __shfl_xor_sync(0xffffffffu, ss, o);
    __shared__ float sacc[4];
    if ((t&31)==0) sacc[t>>5] = ss;
    __syncthreads();
    float tot = sacc[0]+sacc[1]+sacc[2]+sacc[3];
    float rinv = rsqrtf(tot*(1.0f/(float)DMODEL) + EPSV);
    const float4* w4 = (const float4*)w;
    float4 wv = w4[t];
    float o0=v.x*rinv*wv.x, o1=v.y*rinv*wv.y, o2=v.z*rinv*wv.z, o3=v.w*rinv*wv.w;
    OutT* op = out + (size_t)row*DMODEL + t*4;
    op[0]=(OutT)o0; op[1]=(OutT)o1; op[2]=(OutT)o2; op[3]=(OutT)o3;
}

// ---------------- weight conversions ----------------
__global__ void f2b_kernel(const float* __restrict__ in, __nv_bfloat16* __restrict__ out, int n)
{
    int i = blockIdx.x*256 + threadIdx.x;
    if (i < n) out[i] = __float2bfloat16(in[i]);
}

// W_comb = W_dt[1024,32] @ W_xproj[:32, 1024]  -> bf16 [1024,1024]
__global__ void wcomb_kernel(const float* __restrict__ W_dt, const float* __restrict__ W_xproj)
{
    int idx = blockIdx.x*256 + threadIdx.x;   // over 1024*1024
    int i = idx >> 10, j = idx & 1023;
    float s = 0.f;
    #pragma unroll
    for (int r=0;r<32;r++) s = fmaf(W_dt[i*32+r], W_xproj[r*DINNER + j], s);
    g_Wcomb_b[idx] = __float2bfloat16(s);
}

// ---------------- depthwise causal conv (both directions) + bias + silu -> bf16 ----------------
__global__ void conv_kernel(const float* __restrict__ cw, const float* __restrict__ cb)
{
    int idx = blockIdx.x*256 + threadIdx.x;      // over ROWS*DINNER
    if (idx >= ROWS*DINNER) return;
    int d = idx & (DINNER-1);
    int r = idx >> 10;
    int l = r & (LSEQ-1);
    int b = r >> 10;
    float w0=cw[d*4+0], w1=cw[d*4+1], w2=cw[d*4+2], w3=cw[d*4+3];
    float bias = cb[d];
    const float* up = g_xz + (size_t)(b<<10)*(2*DINNER) + d;
    auto U = [&](int li)->float{ return (li>=0 && li<LSEQ) ? up[(size_t)li*(2*DINNER)] : 0.0f; };
    float um3=U(l-3), um2=U(l-2), um1=U(l-1), u0=U(l), up1=U(l+1), up2=U(l+2), up3=U(l+3);
    float f  = bias + w0*um3 + w1*um2 + w2*um1 + w3*u0;
    float bw = bias + w3*u0  + w2*up1 + w1*up2 + w0*up3;
    g_u_b[0][idx] = __float2bfloat16(siluf_(f));
    g_u_b[1][idx] = __float2bfloat16(siluf_(bw));
}

// ---------------- selective scan: one warp per (dir, b, d) ----------------
__global__ void scan_kernel(const float* __restrict__ A_log, const float* __restrict__ Dskip)
{
    int w    = (blockIdx.x*blockDim.x + threadIdx.x) >> 5;
    int lane = threadIdx.x & 31;
    int dir  = w >> 11;
    int rem  = w & 2047;
    int b    = rem >> 10;
    int d    = rem & 1023;
    const float* dtp = g_dt[dir];
    const __nv_bfloat16* up = g_u_b[dir];
    const float* xd  = g_xdbl[dir];
    __nv_bfloat16* gp = g_gate_b[dir];

    int n0 = lane*2;
    float a0 = -expf(A_log[d*DSTATE + n0]);
    float a1 = -expf(A_log[d*DSTATE + n0 + 1]);
    float dsk = Dskip[d];
    float s0 = 0.f, s1 = 0.f;
    int base_r = b << 10;

    for (int t=0; t<LSEQ; t++){
        int l = dir ? (LSEQ-1-t) : t;
        int r = base_r + l;
        float dtv = __ldg(&dtp[(size_t)r*DINNER + d]);
        float uu  = __bfloat162float(up[(size_t)r*DINNER + d]);
        float2 Bv = *(const float2*)&xd[(size_t)r*128 + n0];
        float2 Cv = *(const float2*)&xd[(size_t)r*128 + 64 + n0];
        float dA0 = __expf(dtv*a0);
        float dA1 = __expf(dtv*a1);
        float dtu = dtv*uu;
        s0 = fmaf(s0, dA0, dtu*Bv.x);
        s1 = fmaf(s1, dA1, dtu*Bv.y);
        float p = s0*Cv.x + s1*Cv.y;
        #pragma unroll
        for (int o=16;o;o>>=1) p += __shfl_xor_sync(0xffffffffu, p, o);
        if (lane==0){
            float z = g_xz[(size_t)r*(2*DINNER) + DINNER + d];
            float y = p + uu*dsk;
            gp[(size_t)r*DINNER + d] = __float2bfloat16(y * (z/(1.0f+__expf(-z))));
        }
    }
}

// ---------------- GLU gate + silu -> bf16 ----------------
__global__ void glu_kernel()
{
    int idx = blockIdx.x*256 + threadIdx.x;    // over ROWS*DMODEL
    if (idx >= ROWS*DMODEL) return;
    int r = idx >> 9;
    int d = idx & (DMODEL-1);
    float ug = g_uv[(size_t)r*(2*DMODEL) + d];
    float vg = g_uv[(size_t)r*(2*DMODEL) + DMODEL + d];
    float h  = ug * sigmoidf_(vg);
    g_h2_b[idx] = __float2bfloat16(siluf_(h));
}

// ---------------- host side ----------------
template<typename T>
static T* sym_addr(const void* sym)
{
    void* p = nullptr;
    cudaGetSymbolAddress(&p, sym);
    return (T*)p;
}

extern "C" void kernel_launch(void* const* d_in, const int* in_sizes, int n_in,
                              void* d_out, int out_size)
{
    const float* x       = (const float*)d_in[0];
    const float* W_in    = (const float*)d_in[1];
    const float* conv_w  = (const float*)d_in[2];
    const float* conv_b  = (const float*)d_in[3];
    const float* W_xproj = (const float*)d_in[4];
    const float* W_dt    = (const float*)d_in[5];
    const float* b_dt    = (const float*)d_in[6];
    const float* A_log   = (const float*)d_in[7];
    const float* Dskip   = (const float*)d_in[8];
    const float* W_out   = (const float*)d_in[9];
    const float* nin_w   = (const float*)d_in[10];
    const float* fuse_W  = (const float*)d_in[11];
    const float* fuse_b  = (const float*)d_in[12];
    const float* ff_W1   = (const float*)d_in[13];
    const float* ff_W2   = (const float*)d_in[14];
    const float* nout_w  = (const float*)d_in[15];
    float* out = (float*)d_out;

    __nv_bfloat16* p_h    = sym_addr<__nv_bfloat16>(g_h_b);
    float*         p_xz   = sym_addr<float>(g_xz);
    __nv_bfloat16* p_u    = sym_addr<__nv_bfloat16>(g_u_b);
    float*         p_xdbl = sym_addr<float>(g_xdbl);
    float*         p_dt   = sym_addr<float>(g_dt);
    __nv_bfloat16* p_gate = sym_addr<__nv_bfloat16>(g_gate_b);
    __nv_bfloat16* p_hcat = sym_addr<__nv_bfloat16>(g_hcat_b);
    float*         p_uv   = sym_addr<float>(g_uv);
    __nv_bfloat16* p_h2   = sym_addr<__nv_bfloat16>(g_h2_b);
    __nv_bfloat16* p_ff1  = sym_addr<__nv_bfloat16>(g_ff1_b);
    float*         p_ff2  = sym_addr<float>(g_ff2);
    __nv_bfloat16* p_Win  = sym_addr<__nv_bfloat16>(g_Win_b);
    __nv_bfloat16* p_Wxp  = sym_addr<__nv_bfloat16>(g_Wxp_b);
    __nv_bfloat16* p_Wcb  = sym_addr<__nv_bfloat16>(g_Wcomb_b);
    __nv_bfloat16* p_Wout = sym_addr<__nv_bfloat16>(g_Wout_b);
    __nv_bfloat16* p_Wfu  = sym_addr<__nv_bfloat16>(g_fuse_b);
    __nv_bfloat16* p_Wf1  = sym_addr<__nv_bfloat16>(g_ff1w_b);
    __nv_bfloat16* p_Wf2  = sym_addr<__nv_bfloat16>(g_ff2w_b);

    cudaFuncSetAttribute(tc_gemm<0,float>,         cudaFuncAttributeMaxDynamicSharedMemorySize, GEMM_SMEM);
    cudaFuncSetAttribute(tc_gemm<2,float>,         cudaFuncAttributeMaxDynamicSharedMemorySize, GEMM_SMEM);
    cudaFuncSetAttribute(tc_gemm<3,float>,         cudaFuncAttributeMaxDynamicSharedMemorySize, GEMM_SMEM);
    cudaFuncSetAttribute(tc_gemm<0,__nv_bfloat16>, cudaFuncAttributeMaxDynamicSharedMemorySize, GEMM_SMEM);
    cudaFuncSetAttribute(tc_gemm<1,__nv_bfloat16>, cudaFuncAttributeMaxDynamicSharedMemorySize, GEMM_SMEM);

    dim3 blk(256);

    // 0. weight conversions (fp32 -> bf16) + combined dt weight
    f2b_kernel<<<(2*DINNER*DMODEL+255)/256, blk>>>(W_in,  p_Win, 2*DINNER*DMODEL);
    f2b_kernel<<<(128*DINNER+255)/256,      blk>>>(W_xproj + DTRANK*DINNER, p_Wxp, 128*DINNER);
    f2b_kernel<<<(DMODEL*DINNER+255)/256,   blk>>>(W_out, p_Wout, DMODEL*DINNER);
    f2b_kernel<<<(4*DMODEL*DMODEL+255)/256, blk>>>(fuse_W, p_Wfu, 4*DMODEL*DMODEL);
    f2b_kernel<<<(4*DMODEL*DMODEL+255)/256, blk>>>(ff_W1, p_Wf1, 4*DMODEL*DMODEL);
    f2b_kernel<<<(4*DMODEL*DMODEL+255)/256, blk>>>(ff_W2, p_Wf2, 4*DMODEL*DMODEL);
    wcomb_kernel<<<(DINNER*DINNER)/256, blk>>>(W_dt, W_xproj);

    // 1. h = rmsnorm(x) -> bf16
    rmsnorm_kernel<__nv_bfloat16><<<ROWS, 128>>>(x, nullptr, nin_w, p_h);

    // 2. xz = h @ W_in^T   (N=2048, K=512) -> fp32
    tc_gemm<0,float><<<dim3(16,16), blk, GEMM_SMEM>>>(p_h, p_Win, nullptr, p_xz, 2*DINNER, DMODEL);

    // 3. conv + silu, both directions -> bf16
    conv_kernel<<<(ROWS*DINNER)/256, blk>>>(conv_w, conv_b);

    // 4/5. per direction: [B|C] and dt
    for (int dir=0; dir<2; dir++){
        __nv_bfloat16* u_d = p_u + (size_t)dir*ROWS*DINNER;
        // x_dbl[B|C] = u @ Wxp[32:160]^T  (N=128, K=1024) -> fp32
        tc_gemm<0,float><<<dim3(1,16), blk, GEMM_SMEM>>>(u_d, p_Wxp, nullptr,
                                                         p_xdbl + (size_t)dir*ROWS*128, 128, DINNER);
        // dt = softplus(u @ Wcomb^T + b_dt)  (N=1024, K=1024) -> fp32
        tc_gemm<2,float><<<dim3(8,16), blk, GEMM_SMEM>>>(u_d, p_Wcb, b_dt,
                                                         p_dt + (size_t)dir*ROWS*DINNER, DINNER, DINNER);
    }

    // 6. selective scan -> gate bf16
    scan_kernel<<<512, 256>>>(A_log, Dskip);

    // 7. hcat[:, dir*512:] = gate @ W_out^T  (N=512, K=1024) -> bf16
    for (int dir=0; dir<2; dir++){
        tc_gemm<0,__nv_bfloat16><<<dim3(4,16), blk, GEMM_SMEM>>>(
            p_gate + (size_t)dir*ROWS*DINNER, p_Wout, nullptr,
            p_hcat + dir*DMODEL, 2*DMODEL, DINNER);
    }

    // 8. uv = hcat @ fuse_W^T + fuse_b  (N=1024, K=1024) -> fp32
    tc_gemm<3,float><<<dim3(8,16), blk, GEMM_SMEM>>>(p_hcat, p_Wfu, fuse_b, p_uv, 2*DMODEL, 2*DMODEL);

    // 9. h2 = silu(ug * sigmoid(vg)) -> bf16
    glu_kernel<<<(ROWS*DMODEL)/256, blk>>>();

    // 10. ff1 = silu(h2 @ ff_W1^T)  (N=2048, K=512) -> bf16
    tc_gemm<1,__nv_bfloat16><<<dim3(16,16), blk, GEMM_SMEM>>>(p_h2, p_Wf1, nullptr, p_ff1, 4*DMODEL, DMODEL);

    // 11. ff2 = ff1 @ ff_W2^T  (N=512, K=2048) -> fp32
    tc_gemm<0,float><<<dim3(4,16), blk, GEMM_SMEM>>>(p_ff1, p_Wf2, nullptr, p_ff2, DMODEL, 4*DMODEL);

    // 12. out = rmsnorm(x + ff2)
    rmsnorm_kernel<float><<<ROWS, 128>>>(x, p_ff2, nout_w, out);
}

// round 6
// speedup vs baseline: 1.9332x; 1.1545x over previous
#include <cuda_runtime.h>
#include <cuda_bf16.h>
#include <math.h>
#include <stdint.h>

// ---------------- problem constants ----------------
#define BATCH   2
#define LSEQ    1024
#define DMODEL  512
#define DINNER  1024
#define DSTATE  64
#define DTRANK  32
#define ROWS    (BATCH*LSEQ)          // 2048
#define EPSV    1e-6f

// ---------------- scratch (device globals; no allocations allowed) ----------------
__device__ __align__(16) __nv_bfloat16 g_h_b   [ROWS*DMODEL];      // rmsnorm(x) bf16
__device__ __align__(16) float         g_xz    [ROWS*2*DINNER];    // h @ W_in^T (u | z) fp32
__device__ __align__(16) __nv_bfloat16 g_u_b   [2][ROWS*DINNER];   // conv+silu bf16
__device__ __align__(16) float         g_xdbl  [2][ROWS*128];      // [B|C] fp32 (128 cols)
__device__ __align__(16) float         g_dt    [2][ROWS*DINNER];   // softplus(dt) fp32
__device__ __align__(16) __nv_bfloat16 g_gate_b[2][ROWS*DINNER];   // (y+u*D)*silu(z) bf16
__device__ __align__(16) __nv_bfloat16 g_hcat_b[ROWS*2*DMODEL];    // [hf|hb] bf16
__device__ __align__(16) float         g_uv    [ROWS*2*DMODEL];    // fuse out fp32
__device__ __align__(16) __nv_bfloat16 g_h2_b  [ROWS*DMODEL];      // silu(glu) bf16
__device__ __align__(16) __nv_bfloat16 g_ff1_b [ROWS*4*DMODEL];    // silu(ff1) bf16
__device__ __align__(16) float         g_ff2   [ROWS*DMODEL];      // ff2 fp32
// bf16 weights
__device__ __align__(16) __nv_bfloat16 g_Win_b [2*DINNER*DMODEL];
__device__ __align__(16) __nv_bfloat16 g_Wcat_b[(DINNER+128)*DINNER]; // [Wcomb(1024) | Wxp(128)] rows
__device__ __align__(16) __nv_bfloat16 g_Wout_b[DMODEL*DINNER];
__device__ __align__(16) __nv_bfloat16 g_fuse_b[2*DMODEL*2*DMODEL];
__device__ __align__(16) __nv_bfloat16 g_ff1w_b[4*DMODEL*DMODEL];
__device__ __align__(16) __nv_bfloat16 g_ff2w_b[DMODEL*4*DMODEL];

// ---------------- math helpers ----------------
__device__ __forceinline__ float sigmoidf_(float x){ return 1.0f/(1.0f+expf(-x)); }
__device__ __forceinline__ float siluf_(float x){ return x/(1.0f+expf(-x)); }
__device__ __forceinline__ float softplusf_(float x){ return (x>20.0f)? x : log1pf(expf(x)); }

__device__ __forceinline__ uint32_t smem_u32_(const void* p){
    uint32_t a;
    asm("{ .reg .u64 t; cvta.to.shared.u64 t, %1; cvt.u32.u64 %0, t; }" : "=r"(a) : "l"(p));
    return a;
}

// ---------------- mma.sync bf16 GEMM: C[M,N] = A[M,K](bf16) @ W[N,K](bf16)^T ----------------
// 128x128 CTA tile, 8 warps (2 x 4), warp tile 64x32.
// K chunk = 64, 3-stage cp.async pipeline, one __syncthreads per chunk.
// smem rows padded to 72 bf16 (144B).
// EPI: 0 none, 1 silu, 3 +bias, 4 split(dt: softplus+bias | BC: none -> C2)
#define KCHUNK  64
#define SROW    72
#define CHUNK_BYTES (128*SROW*2)          // 18432 per matrix per stage
#define NSTAGE  3
#define GEMM_SMEM (NSTAGE*2*CHUNK_BYTES)  // 110592

__device__ __forceinline__ void ldsm_x4(uint32_t& r0, uint32_t& r1, uint32_t& r2, uint32_t& r3, uint32_t a){
    asm volatile("ldmatrix.sync.aligned.m8n8.x4.shared.b16 {%0,%1,%2,%3},[%4];"
                 : "=r"(r0),"=r"(r1),"=r"(r2),"=r"(r3) : "r"(a));
}
__device__ __forceinline__ void ldsm_x2(uint32_t& r0, uint32_t& r1, uint32_t a){
    asm volatile("ldmatrix.sync.aligned.m8n8.x2.shared.b16 {%0,%1},[%2];"
                 : "=r"(r0),"=r"(r1) : "r"(a));
}
__device__ __forceinline__ void mma16816(float* d, const uint32_t* a, const uint32_t* b){
    asm volatile("mma.sync.aligned.m16n8k16.row.col.f32.bf16.bf16.f32 "
                 "{%0,%1,%2,%3},{%4,%5,%6,%7},{%8,%9},{%0,%1,%2,%3};"
                 : "+f"(d[0]),"+f"(d[1]),"+f"(d[2]),"+f"(d[3])
                 : "r"(a[0]),"r"(a[1]),"r"(a[2]),"r"(a[3]), "r"(b[0]),"r"(b[1]));
}

template<int EPI, typename OutT>
__global__ void __launch_bounds__(256)
tc_gemm(const __nv_bfloat16* __restrict__ A,
        const __nv_bfloat16* __restrict__ W,
        const float* __restrict__ bias,
        OutT* __restrict__ C, int ldc, int K,
        size_t zsA, size_t zsC,
        float* __restrict__ C2, size_t zsC2)
{
    extern __shared__ char smem[];
    uint32_t sb = smem_u32_(smem);
    int tid = threadIdx.x, lane = tid & 31, w = tid >> 5;
    int wm = w >> 2, wn = w & 3;              // 2 x 4 warp grid
    int m0 = blockIdx.y*128, n0 = blockIdx.x*128;

    A += (size_t)blockIdx.z * zsA;
    C += (size_t)blockIdx.z * zsC;
    if (EPI==4) C2 += (size_t)blockIdx.z * zsC2;

    const __nv_bfloat16* Abase = A + (size_t)m0*K;
    const __nv_bfloat16* Wbase = W + (size_t)n0*K;
    const int NC = K / KCHUNK;

    auto load_chunk = [&](int c, int s){
        uint32_t abuf = sb + (uint32_t)s*2*CHUNK_BYTES;
        uint32_t bbuf = abuf + CHUNK_BYTES;
        const __nv_bfloat16* Ag = Abase + c*KCHUNK;
        const __nv_bfloat16* Wg = Wbase + c*KCHUNK;
        #pragma unroll
        for (int i=0;i<4;i++){
            int idx = i*256 + tid;            // 0..1023
            int r = idx>>3, cc = idx&7;
            uint32_t dst = (uint32_t)(r*(SROW*2) + cc*16);
            asm volatile("cp.async.cg.shared.global [%0],[%1],16;"
                         :: "r"(abuf+dst), "l"((const void*)(Ag + (size_t)r*K + cc*8)));
            asm volatile("cp.async.cg.shared.global [%0],[%1],16;"
                         :: "r"(bbuf+dst), "l"((const void*)(Wg + (size_t)r*K + cc*8)));
        }
        asm volatile("cp.async.commit_group;");
    };

    float acc[4][4][4];
    #pragma unroll
    for (int i=0;i<4;i++)
        #pragma unroll
        for (int j=0;j<4;j++)
            #pragma unroll
            for (int q=0;q<4;q++) acc[i][j][q]=0.f;

    int a_row  = wm*64 + (lane & 15);
    int a_koff = (lane >> 4) * 8;
    int b_row  = wn*32 + (lane & 7);
    int b_koff = ((lane >> 3) & 1) * 8;

    load_chunk(0,0);
    if (NC>1) load_chunk(1,1);

    for (int c=0;c<NC;c++){
        int s = c % NSTAGE;
        if (c+1<NC) asm volatile("cp.async.wait_group 1;" ::: "memory");
        else        asm volatile("cp.async.wait_group 0;" ::: "memory");
        __syncthreads();
        if (c+2<NC) load_chunk(c+2, (c+2)%NSTAGE);
        uint32_t abuf = sb + (uint32_t)s*2*CHUNK_BYTES;
        uint32_t bbuf = abuf + CHUNK_BYTES;
        #pragma unroll
        for (int ks=0; ks<KCHUNK/16; ks++){
            uint32_t afr[4][4], bfr[4][2];
            #pragma unroll
            for (int mt=0;mt<4;mt++){
                uint32_t addr = abuf + (uint32_t)(((a_row + mt*16)*SROW + ks*16 + a_koff)*2);
                ldsm_x4(afr[mt][0],afr[mt][1],afr[mt][2],afr[mt][3], addr);
            }
            #pragma unroll
            for (int nt=0;nt<4;nt++){
                uint32_t addr = bbuf + (uint32_t)(((b_row + nt*8)*SROW + ks*16 + b_koff)*2);
                ldsm_x2(bfr[nt][0],bfr[nt][1], addr);
            }
            #pragma unroll
            for (int mt=0;mt<4;mt++)
                #pragma unroll
                for (int nt=0;nt<4;nt++)
                    mma16816(acc[mt][nt], afr[mt], bfr[nt]);
        }
    }

    // epilogue
    bool bc_side = (EPI==4) && (n0 >= DINNER);  // BC columns -> C2
    float* Cf = bc_side ? C2 : (float*)C;       // only used when OutT==float
    int ldout = bc_side ? 128 : ldc;
    int colShift = bc_side ? DINNER : 0;

    int rbase = m0 + wm*64 + (lane>>2);
    int cbase = n0 + wn*32 + (lane&3)*2;
    #pragma unroll
    for (int mt=0;mt<4;mt++){
        #pragma unroll
        for (int nt=0;nt<4;nt++){
            int col = cbase + nt*8;
            float v[4];
            #pragma unroll
            for (int q=0;q<4;q++){
                float x = acc[mt][nt][q];
                int cc = col + (q&1);
                if (EPI==1) x = siluf_(x);
                else if (EPI==3) x = x + bias[cc];
                else if (EPI==4){ if (!bc_side) x = softplusf_(x + bias[cc]); }
                v[q] = x;
            }
            int r0 = rbase + mt*16, r1 = r0 + 8;
            if (sizeof(OutT)==4){
                int oc = col - colShift;
                *(float2*)(Cf + (size_t)r0*ldout + oc) = make_float2(v[0],v[1]);
                *(float2*)(Cf + (size_t)r1*ldout + oc) = make_float2(v[2],v[3]);
            } else {
                *(__nv_bfloat162*)((__nv_bfloat16*)C + (size_t)r0*ldc + col) = __floats2bfloat162_rn(v[0],v[1]);
                *(__nv_bfloat162*)((__nv_bfloat16*)C + (size_t)r1*ldc + col) = __floats2bfloat162_rn(v[2],v[3]);
            }
        }
    }
}

// ---------------- rmsnorm ----------------
template<typename OutT>
__global__ void rmsnorm_kernel(const float* __restrict__ x,
                               const float* __restrict__ addsrc,
                               const float* __restrict__ w,
                               OutT* __restrict__ out)
{
    int row = blockIdx.x;
    int t = threadIdx.x;
    const float4* x4 = (const float4*)(x + (size_t)row*DMODEL);
    float4 v = x4[t];
    if (addsrc){
        const float4* a4 = (const float4*)(addsrc + (size_t)row*DMODEL);
        float4 a = a4[t];
        v.x+=a.x; v.y+=a.y; v.z+=a.z; v.w+=a.w;
    }
    float ss = v.x*v.x + v.y*v.y + v.z*v.z + v.w*v.w;
    #pragma unroll
    for (int o=16;o;o>>=1) ss += __shfl_xor_sync(0xffffffffu, ss, o);
    __shared__ float sacc[4];
    if ((t&31)==0) sacc[t>>5] = ss;
    __syncthreads();
    float tot = sacc[0]+sacc[1]+sacc[2]+sacc[3];
    float rinv = rsqrtf(tot*(1.0f/(float)DMODEL) + EPSV);
    const float4* w4 = (const float4*)w;
    float4 wv = w4[t];
    float o0=v.x*rinv*wv.x, o1=v.y*rinv*wv.y, o2=v.z*rinv*wv.z, o3=v.w*rinv*wv.w;
    OutT* op = out + (size_t)row*DMODEL + t*4;
    op[0]=(OutT)o0; op[1]=(OutT)o1; op[2]=(OutT)o2; op[3]=(OutT)o3;
}

// ---------------- single-kernel weight conversion (vectorized) ----------------
#define NV_WIN  (2*DINNER*DMODEL/4)     // 262144
#define NV_WXP  (128*DINNER/4)          // 32768
#define NV_WOUT (DMODEL*DINNER/4)       // 131072
#define NV_FUSE (4*DMODEL*DMODEL/4)     // 262144
#define NV_TOT  (NV_WIN+NV_WXP+NV_WOUT+3*NV_FUSE)

__device__ __forceinline__ void cvt4(const float* s, __nv_bfloat16* d, int i){
    float4 v = ((const float4*)s)[i];
    ((__nv_bfloat162*)d)[2*i  ] = __floats2bfloat162_rn(v.x, v.y);
    ((__nv_bfloat162*)d)[2*i+1] = __floats2bfloat162_rn(v.z, v.w);
}
__global__ void convert_all(const float* __restrict__ W_in,
                            const float* __restrict__ W_xproj,
                            const float* __restrict__ W_out,
                            const float* __restrict__ fuse_W,
                            const float* __restrict__ ff_W1,
                            const float* __restrict__ ff_W2)
{
    int i = blockIdx.x*256 + threadIdx.x;
    if (i >= NV_TOT) return;
    if (i < NV_WIN){ cvt4(W_in, g_Win_b, i); return; }
    i -= NV_WIN;
    if (i < NV_WXP){ cvt4(W_xproj + DTRANK*DINNER, g_Wcat_b + DINNER*DINNER, i); return; }
    i -= NV_WXP;
    if (i < NV_WOUT){ cvt4(W_out, g_Wout_b, i); return; }
    i -= NV_WOUT;
    if (i < NV_FUSE){ cvt4(fuse_W, g_fuse_b, i); return; }
    i -= NV_FUSE;
    if (i < NV_FUSE){ cvt4(ff_W1, g_ff1w_b, i); return; }
    i -= NV_FUSE;
    cvt4(ff_W2, g_ff2w_b, i);
}

// W_comb = W_dt[1024,32] @ W_xproj[:32, 1024] -> rows 0..1023 of W_cat
__global__ void wcomb_kernel(const float* __restrict__ W_dt, const float* __restrict__ W_xproj)
{
    int idx = blockIdx.x*256 + threadIdx.x;   // over 1024*1024
    int i = idx >> 10, j = idx & 1023;
    float s = 0.f;
    #pragma unroll
    for (int r=0;r<32;r++) s = fmaf(W_dt[i*32+r], W_xproj[r*DINNER + j], s);
    g_Wcat_b[idx] = __float2bfloat16(s);
}

// ---------------- depthwise causal conv (both directions) + bias + silu -> bf16 ----------------
__global__ void conv_kernel(const float* __restrict__ cw, const float* __restrict__ cb)
{
    int idx = blockIdx.x*256 + threadIdx.x;
    if (idx >= ROWS*DINNER) return;
    int d = idx & (DINNER-1);
    int r = idx >> 10;
    int l = r & (LSEQ-1);
    int b = r >> 10;
    float w0=cw[d*4+0], w1=cw[d*4+1], w2=cw[d*4+2], w3=cw[d*4+3];
    float bias = cb[d];
    const float* up = g_xz + (size_t)(b<<10)*(2*DINNER) + d;
    auto U = [&](int li)->float{ return (li>=0 && li<LSEQ) ? up[(size_t)li*(2*DINNER)] : 0.0f; };
    float um3=U(l-3), um2=U(l-2), um1=U(l-1), u0=U(l), up1=U(l+1), up2=U(l+2), up3=U(l+3);
    float f  = bias + w0*um3 + w1*um2 + w2*um1 + w3*u0;
    float bw = bias + w3*u0  + w2*up1 + w1*up2 + w0*up3;
    g_u_b[0][idx] = __float2bfloat16(siluf_(f));
    g_u_b[1][idx] = __float2bfloat16(siluf_(bw));
}

// ---------------- selective scan: one warp per (dir, b, d); pointer-stepped ----------------
__global__ void scan_kernel(const float* __restrict__ A_log, const float* __restrict__ Dskip)
{
    int w    = (blockIdx.x*blockDim.x + threadIdx.x) >> 5;
    int lane = threadIdx.x & 31;
    int dir  = w >> 11;
    int rem  = w & 2047;
    int b    = rem >> 10;
    int d    = rem & 1023;

    int n0 = lane*2;
    float a0 = -expf(A_log[d*DSTATE + n0]);
    float a1 = -expf(A_log[d*DSTATE + n0 + 1]);
    float dsk = Dskip[d];
    float s0 = 0.f, s1 = 0.f;

    int l0 = dir ? (LSEQ-1) : 0;
    intptr_t stp = dir ? -1 : 1;
    size_t r0 = (size_t)(b<<10) + l0;

    const float* dtP = g_dt[dir] + r0*DINNER + d;
    const __nv_bfloat16* uP = g_u_b[dir] + r0*DINNER + d;
    const float* bP  = g_xdbl[dir] + r0*128 + n0;
    const float* zP  = g_xz + r0*(2*DINNER) + DINNER + d;
    __nv_bfloat16* gP = g_gate_b[dir] + r0*DINNER + d;

    intptr_t sD = stp*DINNER, s128 = stp*128, s2D = stp*(2*DINNER);

    for (int t=0; t<LSEQ; t++){
        float dtv = __ldg(dtP);
        float uu  = __bfloat162float(*uP);
        float2 Bv = *(const float2*)bP;
        float2 Cv = *(const float2*)(bP + 64);
        float dA0 = __expf(dtv*a0);
        float dA1 = __expf(dtv*a1);
        float dtu = dtv*uu;
        s0 = fmaf(s0, dA0, dtu*Bv.x);
        s1 = fmaf(s1, dA1, dtu*Bv.y);
        float p = s0*Cv.x + s1*Cv.y;
        #pragma unroll
        for (int o=16;o;o>>=1) p += __shfl_xor_sync(0xffffffffu, p, o);
        if (lane==0){
            float z = *zP;
            float y = p + uu*dsk;
            *gP = __float2bfloat16(y * (z/(1.0f+__expf(-z))));
        }
        dtP += sD; uP += sD; bP += s128; zP += s2D; gP += sD;
    }
}

// ---------------- GLU gate + silu -> bf16 ----------------
__global__ void glu_kernel()
{
    int idx = blockIdx.x*256 + threadIdx.x;
    if (idx >= ROWS*DMODEL) return;
    int r = idx >> 9;
    int d = idx & (DMODEL-1);
    float ug = g_uv[(size_t)r*(2*DMODEL) + d];
    float vg = g_uv[(size_t)r*(2*DMODEL) + DMODEL + d];
    float h  = ug * sigmoidf_(vg);
    g_h2_b[idx] = __float2bfloat16(siluf_(h));
}

// ---------------- host side ----------------
template<typename T>
static T* sym_addr(const void* sym)
{
    void* p = nullptr;
    cudaGetSymbolAddress(&p, sym);
    return (T*)p;
}

extern "C" void kernel_launch(void* const* d_in, const int* in_sizes, int n_in,
                              void* d_out, int out_size)
{
    const float* x       = (const float*)d_in[0];
    const float* W_in    = (const float*)d_in[1];
    const float* conv_w  = (const float*)d_in[2];
    const float* conv_b  = (const float*)d_in[3];
    const float* W_xproj = (const float*)d_in[4];
    const float* W_dt    = (const float*)d_in[5];
    const float* b_dt    = (const float*)d_in[6];
    const float* A_log   = (const float*)d_in[7];
    const float* Dskip   = (const float*)d_in[8];
    const float* W_out   = (const float*)d_in[9];
    const float* nin_w   = (const float*)d_in[10];
    const float* fuse_W  = (const float*)d_in[11];
    const float* fuse_b  = (const float*)d_in[12];
    const float* ff_W1   = (const float*)d_in[13];
    const float* ff_W2   = (const float*)d_in[14];
    const float* nout_w  = (const float*)d_in[15];
    float* out = (float*)d_out;

    __nv_bfloat16* p_h    = sym_addr<__nv_bfloat16>(g_h_b);
    float*         p_xz   = sym_addr<float>(g_xz);
    __nv_bfloat16* p_u    = sym_addr<__nv_bfloat16>(g_u_b);
    float*         p_xdbl = sym_addr<float>(g_xdbl);
    float*         p_dt   = sym_addr<float>(g_dt);
    __nv_bfloat16* p_gate = sym_addr<__nv_bfloat16>(g_gate_b);
    __nv_bfloat16* p_hcat = sym_addr<__nv_bfloat16>(g_hcat_b);
    float*         p_uv   = sym_addr<float>(g_uv);
    __nv_bfloat16* p_h2   = sym_addr<__nv_bfloat16>(g_h2_b);
    __nv_bfloat16* p_ff1  = sym_addr<__nv_bfloat16>(g_ff1_b);
    float*         p_ff2  = sym_addr<float>(g_ff2);
    __nv_bfloat16* p_Win  = sym_addr<__nv_bfloat16>(g_Win_b);
    __nv_bfloat16* p_Wcat = sym_addr<__nv_bfloat16>(g_Wcat_b);
    __nv_bfloat16* p_Wout = sym_addr<__nv_bfloat16>(g_Wout_b);
    __nv_bfloat16* p_Wfu  = sym_addr<__nv_bfloat16>(g_fuse_b);
    __nv_bfloat16* p_Wf1  = sym_addr<__nv_bfloat16>(g_ff1w_b);
    __nv_bfloat16* p_Wf2  = sym_addr<__nv_bfloat16>(g_ff2w_b);

    cudaFuncSetAttribute(tc_gemm<0,float>,         cudaFuncAttributeMaxDynamicSharedMemorySize, GEMM_SMEM);
    cudaFuncSetAttribute(tc_gemm<4,float>,         cudaFuncAttributeMaxDynamicSharedMemorySize, GEMM_SMEM);
    cudaFuncSetAttribute(tc_gemm<3,float>,         cudaFuncAttributeMaxDynamicSharedMemorySize, GEMM_SMEM);
    cudaFuncSetAttribute(tc_gemm<0,__nv_bfloat16>, cudaFuncAttributeMaxDynamicSharedMemorySize, GEMM_SMEM);
    cudaFuncSetAttribute(tc_gemm<1,__nv_bfloat16>, cudaFuncAttributeMaxDynamicSharedMemorySize, GEMM_SMEM);

    dim3 blk(256);

    // 1. weight conversions (one launch) + combined dt weight
    convert_all<<<(NV_TOT+255)/256, blk>>>(W_in, W_xproj, W_out, fuse_W, ff_W1, ff_W2);
    wcomb_kernel<<<(DINNER*DINNER)/256, blk>>>(W_dt, W_xproj);

    // 2. h = rmsnorm(x) -> bf16
    rmsnorm_kernel<__nv_bfloat16><<<ROWS, 128>>>(x, nullptr, nin_w, p_h);

    // 3. xz = h @ W_in^T   (N=2048, K=512) -> fp32
    tc_gemm<0,float><<<dim3(16,16), blk, GEMM_SMEM>>>(p_h, p_Win, nullptr, p_xz, 2*DINNER, DMODEL,
                                                      0, 0, nullptr, 0);

    // 4. conv + silu, both directions -> bf16
    conv_kernel<<<(ROWS*DINNER)/256, blk>>>(conv_w, conv_b);

    // 5. [dt | BC] = u @ Wcat^T  (N=1152, K=1024), both directions via blockIdx.z
    tc_gemm<4,float><<<dim3(9,16,2), blk, GEMM_SMEM>>>(p_u, p_Wcat, b_dt,
                                                       p_dt, DINNER, DINNER,
                                                       (size_t)ROWS*DINNER, (size_t)ROWS*DINNER,
                                                       p_xdbl, (size_t)ROWS*128);

    // 6. selective scan -> gate bf16
    scan_kernel<<<512, 256>>>(A_log, Dskip);

    // 7. hcat[:, dir*512:] = gate @ W_out^T (N=512, K=1024), both dirs via z
    tc_gemm<0,__nv_bfloat16><<<dim3(4,16,2), blk, GEMM_SMEM>>>(p_gate, p_Wout, nullptr,
                                                               p_hcat, 2*DMODEL, DINNER,
                                                               (size_t)ROWS*DINNER, (size_t)DMODEL,
                                                               nullptr, 0);

    // 8. uv = hcat @ fuse_W^T + fuse_b  (N=1024, K=1024) -> fp32
    tc_gemm<3,float><<<dim3(8,16), blk, GEMM_SMEM>>>(p_hcat, p_Wfu, fuse_b, p_uv, 2*DMODEL, 2*DMODEL,
                                                     0, 0, nullptr, 0);

    // 9. h2 = silu(ug * sigmoid(vg)) -> bf16
    glu_kernel<<<(ROWS*DMODEL)/256, blk>>>();

    // 10. ff1 = silu(h2 @ ff_W1^T)  (N=2048, K=512) -> bf16
    tc_gemm<1,__nv_bfloat16><<<dim3(16,16), blk, GEMM_SMEM>>>(p_h2, p_Wf1, nullptr, p_ff1, 4*DMODEL, DMODEL,
                                                              0, 0, nullptr, 0);

    // 11. ff2 = ff1 @ ff_W2^T  (N=512, K=2048) -> fp32
    tc_gemm<0,float><<<dim3(4,16), blk, GEMM_SMEM>>>(p_ff1, p_Wf2, nullptr, p_ff2, DMODEL, 4*DMODEL,
                                                     0, 0, nullptr, 0);

    // 12. out = rmsnorm(x + ff2)
    rmsnorm_kernel<float><<<ROWS, 128>>>(x, p_ff2, nout_w, out);
}